// round 6
// baseline (speedup 1.0000x reference)
#include <cuda_runtime.h>
#include <cuda_bf16.h>

// PatchPlaneApproxLoss: fused 8x8 plane-fit surface normals + mean-abs-diff.
// B=8, H=479, W=639, P=8, FX=518.857, FY=519.469, EPS=1e-6.
// Shear-frame formulation: per output pixel, moments use fixed offsets
// da_k=(k-4)/FX, db_j=(j-4)/FY, so the 3x3 solve is well-conditioned in fp32.

#define Bn 8
#define Hh 479
#define Ww 639
#define TW 32
#define TH 16
#define TX 20   /* ceil(639/32) */
#define TY 30   /* ceil(479/16) */
#define NBLK (Bn * TX * TY)   /* 4800 */
#define NTHREADS 512
#define HALO_H (TH + 7)       /* 23 */
#define HALO_W (TW + 7)       /* 39, padded to 40 in smem */

#define INV_FX (1.0f / 518.857f)
#define INV_FY (1.0f / 519.469f)
#define EPSV   1e-6f

__device__ float g_partials[NBLK];

__global__ __launch_bounds__(NTHREADS)
void plane_loss_kernel(const float* __restrict__ pred, const float* __restrict__ gt)
{
    __shared__ float sD[HALO_H][40];        // depth halo (padded row stride)
    __shared__ float sH[5][HALO_H][TW];     // horiz sums: d2, da*d2, da2*d2, d, da*d

    const int tid = threadIdx.x;
    const int tc  = tid & 31;
    const int tr  = tid >> 5;
    const int bx  = blockIdx.x, by = blockIdx.y, bz = blockIdx.z;

    const int gor = by * TH + tr;       // global output row
    const int goc = bx * TW + tc;       // global output col
    const bool valid = (gor < Hh) && (goc < Ww);

    float nres[2][3];
    const float* imgs[2];
    imgs[0] = pred; imgs[1] = gt;

    #pragma unroll
    for (int im = 0; im < 2; ++im) {
        const float* img = imgs[im] + (size_t)bz * (Hh * Ww);

        // ---- load depth halo (zero-padded) ----
        for (int idx = tid; idx < HALO_H * 40; idx += NTHREADS) {
            int r = idx / 40;
            int c = idx - r * 40;
            int gr = by * TH + r - 4;
            int gc = bx * TW + c - 4;
            float v = 0.0f;
            if (c < HALO_W && gr >= 0 && gr < Hh && gc >= 0 && gc < Ww)
                v = img[gr * Ww + gc];
            sD[r][c] = v;
        }
        __syncthreads();

        // ---- horizontal 8-tap sums with FIXED shear-frame weights da_k=(k-4)/FX ----
        for (int e = tid; e < HALO_H * TW; e += NTHREADS) {
            int r  = e >> 5;
            int oc = e & 31;
            float h1 = 0.f, ha = 0.f, haa = 0.f, hd = 0.f, had = 0.f;
            #pragma unroll
            for (int k = 0; k < 8; ++k) {
                const float da = (float)(k - 4) * INV_FX;   // compile-time constant
                float d  = sD[r][oc + k];
                float d2 = d * d;
                h1 += d2;
                hd += d;
                if (k != 4) {
                    float t = da * d2;
                    ha += t;
                    haa = fmaf(da, t, haa);
                    had = fmaf(da, d, had);
                }
            }
            sH[0][r][oc] = h1;
            sH[1][r][oc] = ha;
            sH[2][r][oc] = haa;
            sH[3][r][oc] = hd;
            sH[4][r][oc] = had;
        }
        __syncthreads();

        // ---- vertical combine -> shear-frame moments -> adjugate solve ----
        float n0 = 0.f, n1 = 0.f, n2 = 0.f;
        if (valid) {
            float Sxx = 0.f, Sxy = 0.f, Sxz = 0.f, Syy = 0.f, Syz = 0.f, Szz = 0.f;
            float Sx = 0.f, Sy = 0.f, Sz = 0.f;
            #pragma unroll
            for (int k = 0; k < 8; ++k) {
                const float db = (float)(k - 4) * INV_FY;   // compile-time constant
                int r = tr + k;
                float h1  = sH[0][r][tc];
                float ha  = sH[1][r][tc];
                float haa = sH[2][r][tc];
                float hd  = sH[3][r][tc];
                float had = sH[4][r][tc];
                Szz += h1;  Sxz += ha;  Sxx += haa;  Sz += hd;  Sx += had;
                if (k != 4) {
                    Syz = fmaf(db, h1, Syz);
                    Syy = fmaf(db * db, h1, Syy);
                    Sxy = fmaf(db, ha, Sxy);
                    Sy  = fmaf(db, hd, Sy);
                }
            }

            // epsilon term: A' + EPS * S*S^T  (exactly congruent to ref's A + EPS*I)
            const float a0 = ((float)goc - 319.5f) * INV_FX;
            const float b0 = ((float)gor - 239.5f) * INV_FY;
            Sxx += EPSV * fmaf(a0, a0, 1.0f);
            Syy += EPSV * fmaf(b0, b0, 1.0f);
            Szz += EPSV;
            Sxy += EPSV * (a0 * b0);
            Sxz -= EPSV * a0;
            Syz -= EPSV * b0;

            // m ∝ adj(A') * b'  (det > 0: SPD by congruence; scale dies in normalize)
            float c00 = Syy * Szz - Syz * Syz;
            float c01 = Sxz * Syz - Sxy * Szz;
            float c02 = Sxy * Syz - Sxz * Syy;
            float c11 = Sxx * Szz - Sxz * Sxz;
            float c12 = Sxy * Sxz - Sxx * Syz;
            float c22 = Sxx * Syy - Sxy * Sxy;
            float mx = c00 * Sx + c01 * Sy + c02 * Sz;
            float my = c01 * Sx + c11 * Sy + c12 * Sz;
            float mz = c02 * Sx + c12 * Sy + c22 * Sz;

            // back-transform: n = S^T m
            n0 = mx;
            n1 = my;
            n2 = mz - a0 * mx - b0 * my;

            float s2 = n0 * n0 + n1 * n1 + n2 * n2;
            float rn = rsqrtf(s2);
            n0 *= rn; n1 *= rn; n2 *= rn;

            // flip: n . xyz = d * m_z  (positive scaling preserved)
            float dc = sD[tr + 4][tc + 4];
            if (dc * mz > 0.0f) { n0 = -n0; n1 = -n1; n2 = -n2; }
            if (!(dc > 0.0f)) { n0 = 0.f; n1 = 0.f; n2 = 0.f; }
        }
        nres[im][0] = n0; nres[im][1] = n1; nres[im][2] = n2;
        __syncthreads();   // smem reused (next image / reduction)
    }

    float t = fabsf(nres[0][0] - nres[1][0])
            + fabsf(nres[0][1] - nres[1][1])
            + fabsf(nres[0][2] - nres[1][2]);

    // ---- deterministic block reduction (reuse sD as scratch) ----
    float* red = &sD[0][0];
    red[tid] = t;
    __syncthreads();
    #pragma unroll
    for (int s = NTHREADS / 2; s > 0; s >>= 1) {
        if (tid < s) red[tid] += red[tid + s];
        __syncthreads();
    }
    if (tid == 0)
        g_partials[(bz * TY + by) * TX + bx] = red[0];
}

__global__ __launch_bounds__(NTHREADS)
void final_reduce_kernel(float* __restrict__ out)
{
    __shared__ double red[NTHREADS];
    double acc = 0.0;
    for (int i = threadIdx.x; i < NBLK; i += NTHREADS)
        acc += (double)g_partials[i];
    red[threadIdx.x] = acc;
    __syncthreads();
    #pragma unroll
    for (int s = NTHREADS / 2; s > 0; s >>= 1) {
        if (threadIdx.x < s) red[threadIdx.x] += red[threadIdx.x + s];
        __syncthreads();
    }
    if (threadIdx.x == 0) {
        const double cnt = (double)Bn * 3.0 * (double)Hh * (double)Ww;
        out[0] = (float)(red[0] / cnt);
    }
}

extern "C" void kernel_launch(void* const* d_in, const int* in_sizes, int n_in,
                              void* d_out, int out_size)
{
    const float* pred = (const float*)d_in[0];
    const float* gt   = (const float*)d_in[1];
    float* out        = (float*)d_out;

    dim3 grid(TX, TY, Bn);
    plane_loss_kernel<<<grid, NTHREADS>>>(pred, gt);
    final_reduce_kernel<<<1, NTHREADS>>>(out);
}

// round 7
// speedup vs baseline: 1.5151x; 1.5151x over previous
#include <cuda_runtime.h>
#include <cuda_bf16.h>

// PatchPlaneApproxLoss: fused 8x8 plane-fit surface normals + mean-abs-diff.
// B=8, H=479, W=639, P=8, FX=518.857, FY=519.469, EPS=1e-6.
// Shear-frame formulation (validated R6: rel_err 6e-6): per output pixel,
// moments use fixed offsets da_k=(k-4)/FX, db_j=(j-4)/FY -> well-conditioned fp32.
// Single fused kernel: both images interleaved, shuffle reductions, last-block
// deterministic final sum (fixed index order => bit-stable across replays).

#define Bn 8
#define Hh 479
#define Ww 639
#define TW 32
#define TH 16
#define TX 20   /* ceil(639/32) */
#define TY 30   /* ceil(479/16) */
#define NBLK (Bn * TX * TY)   /* 4800 */
#define NTHREADS 512
#define HALO_H (TH + 7)       /* 23 */
#define HALO_W (TW + 7)       /* 39, padded to 40 in smem */

#define INV_FX (1.0f / 518.857f)
#define INV_FY (1.0f / 519.469f)
#define EPSV   1e-6f

__device__ float g_partials[NBLK];
__device__ unsigned int g_counter = 0;

__global__ __launch_bounds__(NTHREADS)
void plane_loss_kernel(const float* __restrict__ pred, const float* __restrict__ gt,
                       float* __restrict__ out)
{
    __shared__ float sD[2][HALO_H][40];       // depth halos, both images
    __shared__ float sH[2][5][HALO_H][TW];    // horiz sums: d2, da*d2, da2*d2, d, da*d
    __shared__ float sWarp[16];
    __shared__ double sDW[16];
    __shared__ bool  sLast;

    const int tid  = threadIdx.x;
    const int lane = tid & 31;
    const int wid  = tid >> 5;
    const int tc   = tid & 31;
    const int tr   = tid >> 5;
    const int bx   = blockIdx.x, by = blockIdx.y, bz = blockIdx.z;

    const int gor = by * TH + tr;
    const int goc = bx * TW + tc;
    const bool valid = (gor < Hh) && (goc < Ww);

    const float* imgs[2];
    imgs[0] = pred + (size_t)bz * (Hh * Ww);
    imgs[1] = gt   + (size_t)bz * (Hh * Ww);

    // ---- load both depth halos (zero-padded) ----
    for (int idx = tid; idx < 2 * HALO_H * 40; idx += NTHREADS) {
        int im = idx >= HALO_H * 40;
        int j  = idx - im * (HALO_H * 40);
        int r  = j / 40;
        int c  = j - r * 40;
        int gr = by * TH + r - 4;
        int gc = bx * TW + c - 4;
        float v = 0.0f;
        if (c < HALO_W && gr >= 0 && gr < Hh && gc >= 0 && gc < Ww)
            v = imgs[im][gr * Ww + gc];
        sD[im][r][c] = v;
    }
    __syncthreads();

    // ---- horizontal 8-tap sums, FIXED shear-frame weights da_k=(k-4)/FX ----
    for (int e = tid; e < 2 * HALO_H * TW; e += NTHREADS) {
        int oc = e & 31;
        int rr = e >> 5;                 // 0 .. 2*HALO_H-1
        int im = rr >= HALO_H;
        int r  = rr - im * HALO_H;
        float h1 = 0.f, ha = 0.f, haa = 0.f, hd = 0.f, had = 0.f;
        #pragma unroll
        for (int k = 0; k < 8; ++k) {
            const float da = (float)(k - 4) * INV_FX;   // compile-time constant
            float d  = sD[im][r][oc + k];
            float d2 = d * d;
            h1 += d2;
            hd += d;
            if (k != 4) {
                float t = da * d2;
                ha += t;
                haa = fmaf(da, t, haa);
                had = fmaf(da, d, had);
            }
        }
        sH[im][0][r][oc] = h1;
        sH[im][1][r][oc] = ha;
        sH[im][2][r][oc] = haa;
        sH[im][3][r][oc] = hd;
        sH[im][4][r][oc] = had;
    }
    __syncthreads();

    // ---- vertical combine -> shear-frame moments -> adjugate solve (both images) ----
    float nres[2][3];
    #pragma unroll
    for (int im = 0; im < 2; ++im) {
        float n0 = 0.f, n1 = 0.f, n2 = 0.f;
        if (valid) {
            float Sxx = 0.f, Sxy = 0.f, Sxz = 0.f, Syy = 0.f, Syz = 0.f, Szz = 0.f;
            float Sx = 0.f, Sy = 0.f, Sz = 0.f;
            #pragma unroll
            for (int k = 0; k < 8; ++k) {
                const float db = (float)(k - 4) * INV_FY;   // compile-time constant
                int r = tr + k;
                float h1  = sH[im][0][r][tc];
                float ha  = sH[im][1][r][tc];
                float haa = sH[im][2][r][tc];
                float hd  = sH[im][3][r][tc];
                float had = sH[im][4][r][tc];
                Szz += h1;  Sxz += ha;  Sxx += haa;  Sz += hd;  Sx += had;
                if (k != 4) {
                    Syz = fmaf(db, h1, Syz);
                    Syy = fmaf(db * db, h1, Syy);
                    Sxy = fmaf(db, ha, Sxy);
                    Sy  = fmaf(db, hd, Sy);
                }
            }

            // epsilon: A' + EPS * S*S^T  (congruent to ref's A + EPS*I)
            const float a0 = ((float)goc - 319.5f) * INV_FX;
            const float b0 = ((float)gor - 239.5f) * INV_FY;
            Sxx += EPSV * fmaf(a0, a0, 1.0f);
            Syy += EPSV * fmaf(b0, b0, 1.0f);
            Szz += EPSV;
            Sxy += EPSV * (a0 * b0);
            Sxz -= EPSV * a0;
            Syz -= EPSV * b0;

            // m ∝ adj(A') * b'   (SPD => det>0; scale dies in normalize)
            float c00 = Syy * Szz - Syz * Syz;
            float c01 = Sxz * Syz - Sxy * Szz;
            float c02 = Sxy * Syz - Sxz * Syy;
            float c11 = Sxx * Szz - Sxz * Sxz;
            float c12 = Sxy * Sxz - Sxx * Syz;
            float c22 = Sxx * Syy - Sxy * Sxy;
            float mx = c00 * Sx + c01 * Sy + c02 * Sz;
            float my = c01 * Sx + c11 * Sy + c12 * Sz;
            float mz = c02 * Sx + c12 * Sy + c22 * Sz;

            // back-transform n = S^T m
            n0 = mx;
            n1 = my;
            n2 = mz - a0 * mx - b0 * my;

            float s2 = n0 * n0 + n1 * n1 + n2 * n2;
            float rn = rsqrtf(s2);
            n0 *= rn; n1 *= rn; n2 *= rn;

            // flip: sign(n . xyz) == sign(d * m_z)
            float dc = sD[im][tr + 4][tc + 4];
            if (dc * mz > 0.0f) { n0 = -n0; n1 = -n1; n2 = -n2; }
            if (!(dc > 0.0f)) { n0 = 0.f; n1 = 0.f; n2 = 0.f; }
        }
        nres[im][0] = n0; nres[im][1] = n1; nres[im][2] = n2;
    }

    float t = fabsf(nres[0][0] - nres[1][0])
            + fabsf(nres[0][1] - nres[1][1])
            + fabsf(nres[0][2] - nres[1][2]);

    // ---- block reduction: warp shuffles + one smem stage ----
    #pragma unroll
    for (int o = 16; o > 0; o >>= 1)
        t += __shfl_down_sync(0xffffffffu, t, o);
    if (lane == 0) sWarp[wid] = t;
    __syncthreads();
    if (wid == 0) {
        float s = (lane < 16) ? sWarp[lane] : 0.0f;
        #pragma unroll
        for (int o = 8; o > 0; o >>= 1)
            s += __shfl_down_sync(0xffffffffu, s, o);
        if (lane == 0)
            g_partials[(bz * TY + by) * TX + bx] = s;
    }
    __syncthreads();   // g_partials write is program-ordered before the fence below

    // ---- last block performs the deterministic final reduction ----
    if (tid == 0) {
        __threadfence();
        unsigned int prev = atomicAdd(&g_counter, 1u);
        sLast = (prev == (unsigned)(NBLK - 1));
    }
    __syncthreads();

    if (sLast) {
        double acc = 0.0;
        for (int i = tid; i < NBLK; i += NTHREADS)
            acc += (double)g_partials[i];
        #pragma unroll
        for (int o = 16; o > 0; o >>= 1)
            acc += __shfl_down_sync(0xffffffffu, acc, o);
        if (lane == 0) sDW[wid] = acc;
        __syncthreads();
        if (wid == 0) {
            double s = (lane < 16) ? sDW[lane] : 0.0;
            #pragma unroll
            for (int o = 8; o > 0; o >>= 1)
                s += __shfl_down_sync(0xffffffffu, s, o);
            if (lane == 0) {
                const double cnt = (double)Bn * 3.0 * (double)Hh * (double)Ww;
                out[0] = (float)(s / cnt);
                g_counter = 0;   // reset for next graph replay
            }
        }
    }
}

extern "C" void kernel_launch(void* const* d_in, const int* in_sizes, int n_in,
                              void* d_out, int out_size)
{
    const float* pred = (const float*)d_in[0];
    const float* gt   = (const float*)d_in[1];
    float* out        = (float*)d_out;

    dim3 grid(TX, TY, Bn);
    plane_loss_kernel<<<grid, NTHREADS>>>(pred, gt, out);
}

// round 10
// speedup vs baseline: 1.7864x; 1.1791x over previous
#include <cuda_runtime.h>
#include <cuda_bf16.h>

// PatchPlaneApproxLoss: fused 8x8 plane-fit surface normals + mean-abs-diff.
// B=8, H=479, W=639, P=8, FX=518.857, FY=519.469, EPS=1e-6.
// Shear-frame formulation (validated: rel_err 6e-6). This round: issue-slot
// reduction — float4-packed h-sums (LDS.128), div-free halo loader,
// immediate-offset vertical addressing.

#define Bn 8
#define Hh 479
#define Ww 639
#define TW 32
#define TH 16
#define TX 20   /* ceil(639/32) */
#define TY 30   /* ceil(479/16) */
#define NBLK (Bn * TX * TY)   /* 4800 */
#define NTHREADS 512
#define HALO_H (TH + 7)       /* 23 */
#define HALO_W (TW + 7)       /* 39, padded to 40 in smem */

#define INV_FX (1.0f / 518.857f)
#define INV_FY (1.0f / 519.469f)
#define EPSV   1e-6f

__device__ float g_partials[NBLK];
__device__ unsigned int g_counter = 0;

__global__ __launch_bounds__(NTHREADS)
void plane_loss_kernel(const float* __restrict__ pred, const float* __restrict__ gt,
                       float* __restrict__ out)
{
    __shared__ float  sD[2][HALO_H][40];          // depth halos (row stride 40)
    __shared__ float4 sH4[2][HALO_H * TW];        // {h1, ha, haa, hd} packed
    __shared__ float  sHad[2][HALO_H * TW];       // had
    __shared__ float  sWarp[16];
    __shared__ double sDW[16];
    __shared__ bool   sLast;

    const int tid  = threadIdx.x;
    const int lane = tid & 31;
    const int wid  = tid >> 5;
    const int tc   = lane;
    const int tr   = wid;
    const int bx   = blockIdx.x, by = blockIdx.y, bz = blockIdx.z;

    const int gor = by * TH + tr;
    const int goc = bx * TW + tc;
    const bool valid = (gor < Hh) && (goc < Ww);

    const float* imgs[2];
    imgs[0] = pred + (size_t)bz * (Hh * Ww);
    imgs[1] = gt   + (size_t)bz * (Hh * Ww);

    // ---- halo load: warp-per-row, no integer division ----
    {
        const int gc0 = bx * TW + lane - 4;
        const int gc1 = gc0 + 32;
        for (int r = wid; r < HALO_H; r += 16) {
            int gr = by * TH + r - 4;
            bool rok = (gr >= 0) && (gr < Hh);
            #pragma unroll
            for (int im = 0; im < 2; ++im) {
                float v0 = 0.0f;
                if (rok && gc0 >= 0 && gc0 < Ww) v0 = imgs[im][gr * Ww + gc0];
                sD[im][r][lane] = v0;
                if (lane < 7) {
                    float v1 = 0.0f;
                    if (rok && gc1 < Ww) v1 = imgs[im][gr * Ww + gc1];
                    sD[im][r][lane + 32] = v1;
                }
            }
        }
    }
    __syncthreads();

    // ---- horizontal 8-tap sums, fixed shear-frame weights da_k=(k-4)/FX ----
    // items: 2 images x 23 rows x 32 cols = 1472
    for (int e = tid; e < 2 * HALO_H * TW; e += NTHREADS) {
        int oc = e & 31;
        int rr = e >> 5;                 // 0 .. 2*HALO_H-1
        int im = rr >= HALO_H;
        int r  = rr - im * HALO_H;
        float h1 = 0.f, ha = 0.f, haa = 0.f, hd = 0.f, had = 0.f;
        #pragma unroll
        for (int k = 0; k < 8; ++k) {
            const float da = (float)(k - 4) * INV_FX;   // compile-time constant
            float d  = sD[im][r][oc + k];
            float d2 = d * d;
            h1 += d2;
            hd += d;
            if (k != 4) {
                float t = da * d2;
                ha += t;
                haa = fmaf(da, t, haa);
                had = fmaf(da, d, had);
            }
        }
        sH4[im][r * TW + oc]  = make_float4(h1, ha, haa, hd);
        sHad[im][r * TW + oc] = had;
    }
    __syncthreads();

    // ---- vertical combine -> shear-frame moments -> adjugate solve ----
    float nres[2][3];
    #pragma unroll
    for (int im = 0; im < 2; ++im) {
        float n0 = 0.f, n1 = 0.f, n2 = 0.f;
        if (valid) {
            const float4* __restrict__ hp = &sH4[im][tr * TW + tc];
            const float*  __restrict__ hq = &sHad[im][tr * TW + tc];

            float Sxx = 0.f, Sxy = 0.f, Sxz = 0.f, Syy = 0.f, Syz = 0.f, Szz = 0.f;
            float Sx = 0.f, Sy = 0.f, Sz = 0.f;
            #pragma unroll
            for (int k = 0; k < 8; ++k) {
                const float db = (float)(k - 4) * INV_FY;   // compile-time constant
                float4 h   = hp[k * TW];    // {h1, ha, haa, hd}, immediate offset
                float  had = hq[k * TW];
                Szz += h.x;  Sxz += h.y;  Sxx += h.z;  Sz += h.w;  Sx += had;
                if (k != 4) {
                    Syz = fmaf(db, h.x, Syz);
                    Syy = fmaf(db * db, h.x, Syy);
                    Sxy = fmaf(db, h.y, Sxy);
                    Sy  = fmaf(db, h.w, Sy);
                }
            }

            // epsilon: A' + EPS * S*S^T  (congruent to ref's A + EPS*I)
            const float a0 = ((float)goc - 319.5f) * INV_FX;
            const float b0 = ((float)gor - 239.5f) * INV_FY;
            Sxx += EPSV * fmaf(a0, a0, 1.0f);
            Syy += EPSV * fmaf(b0, b0, 1.0f);
            Szz += EPSV;
            Sxy += EPSV * (a0 * b0);
            Sxz -= EPSV * a0;
            Syz -= EPSV * b0;

            // m ∝ adj(A') * b'   (SPD => det>0; scale dies in normalize)
            float c00 = Syy * Szz - Syz * Syz;
            float c01 = Sxz * Syz - Sxy * Szz;
            float c02 = Sxy * Syz - Sxz * Syy;
            float c11 = Sxx * Szz - Sxz * Sxz;
            float c12 = Sxy * Sxz - Sxx * Syz;
            float c22 = Sxx * Syy - Sxy * Sxy;
            float mx = c00 * Sx + c01 * Sy + c02 * Sz;
            float my = c01 * Sx + c11 * Sy + c12 * Sz;
            float mz = c02 * Sx + c12 * Sy + c22 * Sz;

            // back-transform n = S^T m
            n0 = mx;
            n1 = my;
            n2 = mz - a0 * mx - b0 * my;

            float s2 = n0 * n0 + n1 * n1 + n2 * n2;
            float rn = rsqrtf(s2);
            n0 *= rn; n1 *= rn; n2 *= rn;

            // flip: sign(n . xyz) == sign(d * m_z)
            float dc = sD[im][tr + 4][tc + 4];
            if (dc * mz > 0.0f) { n0 = -n0; n1 = -n1; n2 = -n2; }
            if (!(dc > 0.0f)) { n0 = 0.f; n1 = 0.f; n2 = 0.f; }
        }
        nres[im][0] = n0; nres[im][1] = n1; nres[im][2] = n2;
    }

    float t = fabsf(nres[0][0] - nres[1][0])
            + fabsf(nres[0][1] - nres[1][1])
            + fabsf(nres[0][2] - nres[1][2]);

    // ---- block reduction: warp shuffles + one smem stage ----
    #pragma unroll
    for (int o = 16; o > 0; o >>= 1)
        t += __shfl_down_sync(0xffffffffu, t, o);
    if (lane == 0) sWarp[wid] = t;
    __syncthreads();
    if (wid == 0) {
        float s = (lane < 16) ? sWarp[lane] : 0.0f;
        #pragma unroll
        for (int o = 8; o > 0; o >>= 1)
            s += __shfl_down_sync(0xffffffffu, s, o);
        if (lane == 0)
            g_partials[(bz * TY + by) * TX + bx] = s;
    }
    __syncthreads();

    // ---- last block performs the deterministic final reduction ----
    if (tid == 0) {
        __threadfence();
        unsigned int prev = atomicAdd(&g_counter, 1u);
        sLast = (prev == (unsigned)(NBLK - 1));
    }
    __syncthreads();

    if (sLast) {
        double acc = 0.0;
        for (int i = tid; i < NBLK; i += NTHREADS)
            acc += (double)g_partials[i];
        #pragma unroll
        for (int o = 16; o > 0; o >>= 1)
            acc += __shfl_down_sync(0xffffffffu, acc, o);
        if (lane == 0) sDW[wid] = acc;
        __syncthreads();
        if (wid == 0) {
            double s = (lane < 16) ? sDW[lane] : 0.0;
            #pragma unroll
            for (int o = 8; o > 0; o >>= 1)
                s += __shfl_down_sync(0xffffffffu, s, o);
            if (lane == 0) {
                const double cnt = (double)Bn * 3.0 * (double)Hh * (double)Ww;
                out[0] = (float)(s / cnt);
                g_counter = 0;   // reset for next graph replay
            }
        }
    }
}

extern "C" void kernel_launch(void* const* d_in, const int* in_sizes, int n_in,
                              void* d_out, int out_size)
{
    const float* pred = (const float*)d_in[0];
    const float* gt   = (const float*)d_in[1];
    float* out        = (float*)d_out;

    dim3 grid(TX, TY, Bn);
    plane_loss_kernel<<<grid, NTHREADS>>>(pred, gt, out);
}